// round 5
// baseline (speedup 1.0000x reference)
#include <cuda_runtime.h>
#include <cuda_bf16.h>

// Pairwise max-margin hinge loss.
// relu(v) = (v + |v|)/2, and sum_jk v = N^2*m - 2*(N*sum(o*l) - sum(o)*sum(l))
// is closed-form per batch. The pairwise loop computes only sum |v|, with the
// unordered off-diagonal 32x32 tiles (weight 2) + diagonal tiles (weight 1).
// Inputs: out [N,B] f32, label [N,B] f32, margin [1] f32.  N=1024, B=32.

#define PN 1024
#define PB 32
#define TILE 32
#define BLKS_PER_B 33      // 528 triangle tiles / 16 per block
#define THREADS 256        // 8 warps x 2 tiles/warp = 16 tiles

// Transposed SoA scratch: g_on = -out, g_l = label, laid out [B][N].
__device__ float g_on[PB * PN];
__device__ float g_l [PB * PN];

__global__ __launch_bounds__(256)
void transpose_kernel(const float* __restrict__ g_out,
                      const float* __restrict__ g_label,
                      float* __restrict__ result)
{
    int idx = blockIdx.x * blockDim.x + threadIdx.x;   // 0 .. PN*PB-1
    if (idx < PN * PB) {
        int n = idx >> 5;
        int b = idx & 31;
        g_on[b * PN + n] = -g_out[idx];
        g_l [b * PN + n] =  g_label[idx];
    }
    if (idx == 0) *result = 0.0f;
}

// Packed f32x2 ops on true 64-bit registers.
__device__ __forceinline__ unsigned long long fadd2u(unsigned long long a,
                                                     unsigned long long b) {
    unsigned long long d;
    asm("add.rn.f32x2 %0,%1,%2;" : "=l"(d) : "l"(a), "l"(b));
    return d;
}
__device__ __forceinline__ unsigned long long ffma2u(unsigned long long a,
                                                     unsigned long long b,
                                                     unsigned long long c) {
    unsigned long long d;
    asm("fma.rn.f32x2 %0,%1,%2,%3;" : "=l"(d) : "l"(a), "l"(b), "l"(c));
    return d;
}
__device__ __forceinline__ unsigned long long pack2(float lo, float hi) {
    unsigned long long d;
    asm("mov.b64 %0,{%1,%2};" : "=l"(d) : "f"(lo), "f"(hi));
    return d;
}
__device__ __forceinline__ float2 unpack2(unsigned long long v) {
    float2 r;
    asm("mov.b64 {%0,%1},%2;" : "=f"(r.x), "=f"(r.y) : "l"(v));
    return r;
}

__global__ __launch_bounds__(THREADS)
void hinge_tri_kernel(const float* __restrict__ g_margin,
                      float* __restrict__ result)
{
    __shared__ float s_on[PN];                // -o for this batch
    __shared__ float s_l [PN];                // +l for this batch
    __shared__ float warp_sums[THREADS / 32];
    __shared__ float red[3][THREADS / 32];    // linear-part reduction

    const int batch  = blockIdx.x / BLKS_PER_B;
    const int bshare = blockIdx.x % BLKS_PER_B;   // 0..32
    const int t      = threadIdx.x;
    const int wid    = t >> 5;
    const int lane   = t & 31;

    // Stage: 256 float4 per array, 256 threads -> exactly 1 each.
    {
        const float4* so = (const float4*)(&g_on[batch * PN]);
        const float4* sl = (const float4*)(&g_l [batch * PN]);
        ((float4*)s_on)[t] = so[t];
        ((float4*)s_l )[t] = sl[t];
    }
    __syncthreads();

    const float m = g_margin[0];
    const unsigned long long mm = pack2(m, m);

    float total = 0.0f;

    #pragma unroll
    for (int i = 0; i < 2; i++) {
        const int u = bshare * 16 + wid * 2 + i;      // 0..527

        // Circular-distance decode of unordered tile pairs.
        int jt, kt;
        float w;
        if (u < 480)      { int dt = (u >> 5) + 1; jt = u & 31; kt = (jt + dt) & 31; w = 2.0f; }
        else if (u < 496) { jt = u - 480; kt = jt + 16; w = 2.0f; }
        else              { jt = u - 496; kt = jt;      w = 1.0f; }

        const float oj  = -s_on[jt * TILE + lane];    // +o_j
        const float ljn = -s_l [jt * TILE + lane];    // -l_j
        const unsigned long long ojp  = pack2(oj,  oj);
        const unsigned long long ljnp = pack2(ljn, ljn);
        const int kb = kt * TILE;

        float t0 = 0.0f, t1 = 0.0f, t2 = 0.0f, t3 = 0.0f;

        #pragma unroll
        for (int k = 0; k < TILE; k += 4) {
            // Broadcast LDS.128; reinterpret as two packed f32x2.
            ulonglong2 o2 = *(const ulonglong2*)(&s_on[kb + k]);  // {-ok}
            ulonglong2 l2 = *(const ulonglong2*)(&s_l [kb + k]);  // {+lk}

            // a = oj - ok ; d = lk - lj ; v = m + a*d
            unsigned long long a01 = fadd2u(ojp,  o2.x);
            unsigned long long a23 = fadd2u(ojp,  o2.y);
            unsigned long long d01 = fadd2u(ljnp, l2.x);
            unsigned long long d23 = fadd2u(ljnp, l2.y);
            float2 v01 = unpack2(ffma2u(a01, d01, mm));
            float2 v23 = unpack2(ffma2u(a23, d23, mm));

            // |v| folds into FADD as an operand modifier.
            t0 += fabsf(v01.x);
            t1 += fabsf(v01.y);
            t2 += fabsf(v23.x);
            t3 += fabsf(v23.y);
        }
        total = fmaf(w, (t0 + t1) + (t2 + t3), total);
    }

    // Linear (closed-form) part: per-thread partials on all blocks (cheap),
    // but only bshare==0 reduces and contributes it.
    float4 on4 = ((const float4*)s_on)[t];
    float4 l4  = ((const float4*)s_l )[t];
    float so  = -(on4.x + on4.y + on4.z + on4.w);                 // sum o
    float sl  =  (l4.x + l4.y + l4.z + l4.w);                     // sum l
    float sol = -(on4.x * l4.x + on4.y * l4.y
                  + on4.z * l4.z + on4.w * l4.w);                 // sum o*l
    #pragma unroll
    for (int off = 16; off > 0; off >>= 1) {
        so  += __shfl_xor_sync(0xFFFFFFFFu, so,  off);
        sl  += __shfl_xor_sync(0xFFFFFFFFu, sl,  off);
        sol += __shfl_xor_sync(0xFFFFFFFFu, sol, off);
    }

    // Warp-level |v| reduce.
    #pragma unroll
    for (int off = 16; off > 0; off >>= 1)
        total += __shfl_xor_sync(0xFFFFFFFFu, total, off);

    if (lane == 0) {
        warp_sums[wid] = total;
        red[0][wid] = so; red[1][wid] = sl; red[2][wid] = sol;
    }
    __syncthreads();

    if (t == 0) {
        float s = 0.f;
        #pragma unroll
        for (int wdx = 0; wdx < THREADS / 32; wdx++) s += warp_sums[wdx];
        if (bshare == 0) {
            float So = 0.f, Sl = 0.f, Sol = 0.f;
            #pragma unroll
            for (int wdx = 0; wdx < THREADS / 32; wdx++) {
                So += red[0][wdx]; Sl += red[1][wdx]; Sol += red[2][wdx];
            }
            // S_lin = N^2*m - 2*(N*Sol - So*Sl)
            s += (float)PN * (float)PN * m - 2.0f * ((float)PN * Sol - So * Sl);
        }
        atomicAdd(result, s * (1.0f / (4.0f * PN)));
    }
}

extern "C" void kernel_launch(void* const* d_in, const int* in_sizes, int n_in,
                              void* d_out, int out_size)
{
    const float* g_out    = (const float*)d_in[0];
    const float* g_label  = (const float*)d_in[1];
    const float* g_margin = (const float*)d_in[2];
    float*       result   = (float*)d_out;

    transpose_kernel<<<(PN * PB + 255) / 256, 256>>>(g_out, g_label, result);

    dim3 grid(PB * BLKS_PER_B);   // 1056 blocks
    hinge_tri_kernel<<<grid, THREADS>>>(g_margin, result);
}

// round 7
// speedup vs baseline: 1.0028x; 1.0028x over previous
#include <cuda_runtime.h>
#include <cuda_bf16.h>

// Pairwise max-margin hinge loss.
// relu(v) = (v + |v|)/2; sum_jk v = N^2*m - 2*(N*sum(o*l) - sum(o)*sum(l)) is
// closed-form per batch (computed by one block per batch). The pairwise loop
// computes sum |v| over unordered off-diagonal 32x32 tiles (weight 2) +
// diagonal tiles (weight 1), fully in packed f32x2 with abs via sign-masking.
// Inputs: out [N,B] f32, label [N,B] f32, margin [1] f32.  N=1024, B=32.

#define PN 1024
#define PB 32
#define TILE 32
#define BLKS_PER_B 33      // 528 triangle tiles / 16 per block
#define THREADS 256        // 8 warps x 2 tiles/warp = 16 tiles

#define ABS2MASK 0x7FFFFFFF7FFFFFFFULL

// Transposed SoA scratch: g_on = -out, g_l = label, laid out [B][N].
__device__ float g_on[PB * PN];
__device__ float g_l [PB * PN];

__global__ __launch_bounds__(256)
void transpose_kernel(const float* __restrict__ g_out,
                      const float* __restrict__ g_label,
                      float* __restrict__ result)
{
    int idx = blockIdx.x * blockDim.x + threadIdx.x;   // 0 .. PN*PB-1
    if (idx < PN * PB) {
        int n = idx >> 5;
        int b = idx & 31;
        g_on[b * PN + n] = -g_out[idx];
        g_l [b * PN + n] =  g_label[idx];
    }
    if (idx == 0) *result = 0.0f;
}

// Packed f32x2 ops on true 64-bit registers.
__device__ __forceinline__ unsigned long long fadd2u(unsigned long long a,
                                                     unsigned long long b) {
    unsigned long long d;
    asm("add.rn.f32x2 %0,%1,%2;" : "=l"(d) : "l"(a), "l"(b));
    return d;
}
__device__ __forceinline__ unsigned long long ffma2u(unsigned long long a,
                                                     unsigned long long b,
                                                     unsigned long long c) {
    unsigned long long d;
    asm("fma.rn.f32x2 %0,%1,%2,%3;" : "=l"(d) : "l"(a), "l"(b), "l"(c));
    return d;
}
__device__ __forceinline__ unsigned long long pack2(float lo, float hi) {
    unsigned long long d;
    asm("mov.b64 %0,{%1,%2};" : "=l"(d) : "f"(lo), "f"(hi));
    return d;
}
__device__ __forceinline__ float2 unpack2(unsigned long long v) {
    float2 r;
    asm("mov.b64 {%0,%1},%2;" : "=f"(r.x), "=f"(r.y) : "l"(v));
    return r;
}

__global__ __launch_bounds__(THREADS)
void hinge_tri_kernel(const float* __restrict__ g_margin,
                      float* __restrict__ result)
{
    __shared__ float s_on[PN];                // -o for this batch
    __shared__ float s_l [PN];                // +l for this batch
    __shared__ float warp_sums[THREADS / 32];
    __shared__ float red[3][THREADS / 32];    // linear-part reduction

    const int batch  = blockIdx.x / BLKS_PER_B;
    const int bshare = blockIdx.x % BLKS_PER_B;   // 0..32
    const int t      = threadIdx.x;
    const int wid    = t >> 5;
    const int lane   = t & 31;

    // Stage: 256 float4 per array, 256 threads -> exactly 1 each.
    {
        const float4* so = (const float4*)(&g_on[batch * PN]);
        const float4* sl = (const float4*)(&g_l [batch * PN]);
        ((float4*)s_on)[t] = so[t];
        ((float4*)s_l )[t] = sl[t];
    }
    __syncthreads();

    const float m = g_margin[0];
    const unsigned long long mm = pack2(m, m);

    float total = 0.0f;

    #pragma unroll
    for (int i = 0; i < 2; i++) {
        const int u = bshare * 16 + wid * 2 + i;      // 0..527

        // Circular-distance decode of unordered tile pairs.
        int jt, kt;
        float w;
        if (u < 480)      { int dt = (u >> 5) + 1; jt = u & 31; kt = (jt + dt) & 31; w = 2.0f; }
        else if (u < 496) { jt = u - 480; kt = jt + 16; w = 2.0f; }
        else              { jt = u - 496; kt = jt;      w = 1.0f; }

        const float oj  = -s_on[jt * TILE + lane];    // +o_j
        const float ljn = -s_l [jt * TILE + lane];    // -l_j
        const unsigned long long ojp  = pack2(oj,  oj);
        const unsigned long long ljnp = pack2(ljn, ljn);
        const int kb = kt * TILE;

        unsigned long long accA = 0ULL;   // packed {0.0f, 0.0f}
        unsigned long long accB = 0ULL;

        #pragma unroll
        for (int k = 0; k < TILE; k += 4) {
            // Broadcast LDS.128; reinterpret as two packed f32x2.
            ulonglong2 o2 = *(const ulonglong2*)(&s_on[kb + k]);  // {-ok}
            ulonglong2 l2 = *(const ulonglong2*)(&s_l [kb + k]);  // {+lk}

            // a = oj - ok ; d = lk - lj ; v = m + a*d
            unsigned long long a01 = fadd2u(ojp,  o2.x);
            unsigned long long a23 = fadd2u(ojp,  o2.y);
            unsigned long long d01 = fadd2u(ljnp, l2.x);
            unsigned long long d23 = fadd2u(ljnp, l2.y);
            unsigned long long v01 = ffma2u(a01, d01, mm);
            unsigned long long v23 = ffma2u(a23, d23, mm);

            // |v| via sign-mask, accumulate fully packed.
            accA = fadd2u(accA, v01 & ABS2MASK);
            accB = fadd2u(accB, v23 & ABS2MASK);
        }

        float2 ra = unpack2(accA);
        float2 rb = unpack2(accB);
        total = fmaf(w, (ra.x + ra.y) + (rb.x + rb.y), total);
    }

    // Linear (closed-form) part: only the bshare==0 block of each batch.
    float so = 0.f, sl = 0.f, sol = 0.f;
    if (bshare == 0) {
        float4 on4 = ((const float4*)s_on)[t];
        float4 l4  = ((const float4*)s_l )[t];
        so  = -(on4.x + on4.y + on4.z + on4.w);                 // sum o
        sl  =  (l4.x + l4.y + l4.z + l4.w);                     // sum l
        sol = -(on4.x * l4.x + on4.y * l4.y
                + on4.z * l4.z + on4.w * l4.w);                 // sum o*l
        #pragma unroll
        for (int off = 16; off > 0; off >>= 1) {
            so  += __shfl_xor_sync(0xFFFFFFFFu, so,  off);
            sl  += __shfl_xor_sync(0xFFFFFFFFu, sl,  off);
            sol += __shfl_xor_sync(0xFFFFFFFFu, sol, off);
        }
    }

    // Warp-level |v| reduce.
    #pragma unroll
    for (int off = 16; off > 0; off >>= 1)
        total += __shfl_xor_sync(0xFFFFFFFFu, total, off);

    if (lane == 0) {
        warp_sums[wid] = total;
        red[0][wid] = so; red[1][wid] = sl; red[2][wid] = sol;
    }
    __syncthreads();

    if (t == 0) {
        float s = 0.f;
        #pragma unroll
        for (int wdx = 0; wdx < THREADS / 32; wdx++) s += warp_sums[wdx];
        if (bshare == 0) {
            float So = 0.f, Sl = 0.f, Sol = 0.f;
            #pragma unroll
            for (int wdx = 0; wdx < THREADS / 32; wdx++) {
                So += red[0][wdx]; Sl += red[1][wdx]; Sol += red[2][wdx];
            }
            // S_lin = N^2*m - 2*(N*Sol - So*Sl)
            s += (float)PN * (float)PN * m - 2.0f * ((float)PN * Sol - So * Sl);
        }
        atomicAdd(result, s * (1.0f / (4.0f * PN)));
    }
}

extern "C" void kernel_launch(void* const* d_in, const int* in_sizes, int n_in,
                              void* d_out, int out_size)
{
    const float* g_out    = (const float*)d_in[0];
    const float* g_label  = (const float*)d_in[1];
    const float* g_margin = (const float*)d_in[2];
    float*       result   = (float*)d_out;

    transpose_kernel<<<(PN * PB + 255) / 256, 256>>>(g_out, g_label, result);

    dim3 grid(PB * BLKS_PER_B);   // 1056 blocks
    hinge_tri_kernel<<<grid, THREADS>>>(g_margin, result);
}

// round 8
// speedup vs baseline: 1.0322x; 1.0292x over previous
#include <cuda_runtime.h>
#include <cuda_bf16.h>

// Pairwise max-margin hinge loss.
// One block per unordered 32x32 tile-pair (528 of them), covering ALL 32
// batches. Tile gmem data is contiguous in the native [N,B] layout, so
// staging is fully coalesced and no transpose pre-pass is needed.
// loss = [2*sum_{off-diag tile pairs} + sum_{diag tiles}] / (N*2).
// Inputs: out [N,B] f32, label [N,B] f32, margin [1] f32.  N=1024, B=32.

#define PN 1024
#define PB 32
#define NBLK 528
#define THREADS 256
#define JSTRIDE 33     // conflict-free strided STS + lane-consecutive LDS
#define KSTRIDE 36     // 144B row stride: 16B-aligned for LDS.128 broadcast

// Packed f32x2 helpers on true 64-bit registers.
__device__ __forceinline__ unsigned long long fadd2u(unsigned long long a,
                                                     unsigned long long b) {
    unsigned long long d;
    asm("add.rn.f32x2 %0,%1,%2;" : "=l"(d) : "l"(a), "l"(b));
    return d;
}
__device__ __forceinline__ unsigned long long ffma2u(unsigned long long a,
                                                     unsigned long long b,
                                                     unsigned long long c) {
    unsigned long long d;
    asm("fma.rn.f32x2 %0,%1,%2,%3;" : "=l"(d) : "l"(a), "l"(b), "l"(c));
    return d;
}
__device__ __forceinline__ unsigned long long pack2(float lo, float hi) {
    unsigned long long d;
    asm("mov.b64 %0,{%1,%2};" : "=l"(d) : "f"(lo), "f"(hi));
    return d;
}
__device__ __forceinline__ float2 unpack2(unsigned long long v) {
    float2 r;
    asm("mov.b64 {%0,%1},%2;" : "=f"(r.x), "=f"(r.y) : "l"(v));
    return r;
}

__global__ __launch_bounds__(THREADS)
void hinge_tile_kernel(const float* __restrict__ g_out,
                       const float* __restrict__ g_label,
                       const float* __restrict__ g_margin,
                       float* __restrict__ result)
{
    __shared__ float s_oJ[PB * JSTRIDE];                 // +o, [b][j]
    __shared__ float s_lJ[PB * JSTRIDE];                 // +l, [b][j]
    __shared__ alignas(16) float s_oK[PB * KSTRIDE];     // -o, [b][k]
    __shared__ alignas(16) float s_lK[PB * KSTRIDE];     // +l, [b][k]
    __shared__ float warp_sums[THREADS / 32];

    const int u = blockIdx.x;   // 0..527: unordered tile pair
    int jt, kt;
    float w;
    if (u < 480)      { int dt = (u >> 5) + 1; jt = u & 31; kt = (jt + dt) & 31; w = 2.0f; }
    else if (u < 496) { jt = u - 480; kt = jt + 16; w = 2.0f; }
    else              { jt = u - 496; kt = jt;      w = 1.0f; }

    const int t    = threadIdx.x;
    const int wid  = t >> 5;
    const int lane = t & 31;

    // Stage. Tile jt covers gmem rows [32*jt, 32*jt+32) x all 32 batches
    // = 1024 contiguous floats starting at jt*1024.  Fully coalesced LDG.
    {
        const float* Jo = g_out   + jt * 1024;
        const float* Jl = g_label + jt * 1024;
        const float* Ko = g_out   + kt * 1024;
        const float* Kl = g_label + kt * 1024;
        #pragma unroll
        for (int q = 0; q < 4; q++) {
            int g = t + q * THREADS;        // 0..1023 = n_local*32 + b
            int n = g >> 5;
            int b = g & 31;
            s_oJ[b * JSTRIDE + n] =  Jo[g];
            s_lJ[b * JSTRIDE + n] =  Jl[g];
            s_oK[b * KSTRIDE + n] = -Ko[g];
            s_lK[b * KSTRIDE + n] =  Kl[g];
        }
    }
    __syncthreads();

    const float m = g_margin[0];
    const unsigned long long mm = pack2(m, m);

    float acc = 0.0f;

    // Each warp handles 4 batches; lane = j row within the J tile.
    #pragma unroll
    for (int i = 0; i < 4; i++) {
        const int bb = wid * 4 + i;
        const float oj = s_oJ[bb * JSTRIDE + lane];
        const float lj = s_lJ[bb * JSTRIDE + lane];
        const unsigned long long ojp = pack2(oj, oj);
        const unsigned long long ljn = pack2(-lj, -lj);
        const float* ko = &s_oK[bb * KSTRIDE];
        const float* kl = &s_lK[bb * KSTRIDE];

        float t0 = 0.f, t1 = 0.f, t2 = 0.f, t3 = 0.f;
        #pragma unroll
        for (int kg = 0; kg < 8; kg++) {
            // LDS.128 broadcast (all lanes same address).
            ulonglong2 o2 = *(const ulonglong2*)(ko + kg * 4);   // {-ok}
            ulonglong2 l2 = *(const ulonglong2*)(kl + kg * 4);   // {+lk}

            // a = oj - ok ; d = lk - lj ; v = m + a*d = m - (oj-ok)(lj-lk)
            unsigned long long a01 = fadd2u(ojp, o2.x);
            unsigned long long a23 = fadd2u(ojp, o2.y);
            unsigned long long d01 = fadd2u(ljn, l2.x);
            unsigned long long d23 = fadd2u(ljn, l2.y);
            float2 v01 = unpack2(ffma2u(a01, d01, mm));
            float2 v23 = unpack2(ffma2u(a23, d23, mm));

            t0 += fmaxf(v01.x, 0.0f);
            t1 += fmaxf(v01.y, 0.0f);
            t2 += fmaxf(v23.x, 0.0f);
            t3 += fmaxf(v23.y, 0.0f);
        }
        acc += (t0 + t1) + (t2 + t3);
    }
    acc *= w;

    // Warp reduce.
    #pragma unroll
    for (int off = 16; off > 0; off >>= 1)
        acc += __shfl_xor_sync(0xFFFFFFFFu, acc, off);
    if (lane == 0) warp_sums[wid] = acc;
    __syncthreads();

    if (t == 0) {
        float s = 0.f;
        #pragma unroll
        for (int wdx = 0; wdx < THREADS / 32; wdx++) s += warp_sums[wdx];
        atomicAdd(result, s * (1.0f / (2.0f * PN)));
    }
}

extern "C" void kernel_launch(void* const* d_in, const int* in_sizes, int n_in,
                              void* d_out, int out_size)
{
    const float* g_out    = (const float*)d_in[0];
    const float* g_label  = (const float*)d_in[1];
    const float* g_margin = (const float*)d_in[2];
    float*       result   = (float*)d_out;

    cudaMemsetAsync(result, 0, sizeof(float));
    hinge_tile_kernel<<<NBLK, THREADS>>>(g_out, g_label, g_margin, result);
}

// round 9
// speedup vs baseline: 1.0762x; 1.0427x over previous
#include <cuda_runtime.h>
#include <cuda_fp16.h>
#include <cuda_bf16.h>

// Pairwise max-margin hinge loss, fp16x2 (HFMA2) inner loop.
// One block per unordered 32x32 tile-pair (528), covering ALL 32 batches.
// Native [N,B] layout is contiguous per tile -> coalesced staging, no
// transpose pre-pass.  loss = [2*offdiag + diag] / (N*2).
// Inputs: out [N,B] f32, label [N,B] f32, margin [1] f32.  N=1024, B=32.

#define PN 1024
#define PB 32
#define NBLK 528
#define THREADS 512        // 16 warps; warp w -> batches 2w, 2w+1
#define JSTRIDE 33         // f32 J arrays
#define KSTRIDE 40         // half K arrays: 80B row stride, 16B-aligned

struct __align__(16) H2x4 { __half2 h[4]; };

__global__ __launch_bounds__(THREADS)
void hinge_tile_kernel(const float* __restrict__ g_out,
                       const float* __restrict__ g_label,
                       const float* __restrict__ g_margin,
                       float* __restrict__ result)
{
    __shared__ float  s_oJ[PB * JSTRIDE];               // +o, [b][j], f32
    __shared__ float  s_lJ[PB * JSTRIDE];               // +l, [b][j], f32
    __shared__ alignas(16) __half s_oK[PB * KSTRIDE];   // +o, [b][k], half
    __shared__ alignas(16) __half s_lK[PB * KSTRIDE];   // +l, [b][k], half
    __shared__ float warp_sums[THREADS / 32];

    const int u = blockIdx.x;   // 0..527: unordered tile pair
    int jt, kt;
    float w;
    if (u < 480)      { int dt = (u >> 5) + 1; jt = u & 31; kt = (jt + dt) & 31; w = 2.0f; }
    else if (u < 496) { jt = u - 480; kt = jt + 16; w = 2.0f; }
    else              { jt = u - 496; kt = jt;      w = 1.0f; }

    const int t    = threadIdx.x;
    const int wid  = t >> 5;
    const int lane = t & 31;

    // Stage. Tile r covers gmem [r*1024, r*1024+1024): contiguous, coalesced.
    {
        const float* Jo = g_out   + jt * 1024;
        const float* Jl = g_label + jt * 1024;
        const float* Ko = g_out   + kt * 1024;
        const float* Kl = g_label + kt * 1024;
        #pragma unroll
        for (int q = 0; q < 2; q++) {
            int g = t + q * THREADS;        // 0..1023 = n_local*32 + b
            int n = g >> 5;
            int b = g & 31;
            s_oJ[b * JSTRIDE + n] = Jo[g];
            s_lJ[b * JSTRIDE + n] = Jl[g];
            s_oK[b * KSTRIDE + n] = __float2half(Ko[g]);
            s_lK[b * KSTRIDE + n] = __float2half(Kl[g]);
        }
    }
    __syncthreads();

    const float m = g_margin[0];
    const __half2 m2 = __float2half2_rn(m);
    const __half2 z2 = __float2half2_rn(0.0f);

    float acc = 0.0f;

    // Each warp handles 2 batches; lane = j row within the J tile.
    #pragma unroll
    for (int i = 0; i < 2; i++) {
        const int bb = wid * 2 + i;
        const __half2 oj2 = __float2half2_rn(s_oJ[bb * JSTRIDE + lane]);
        const __half2 lj2 = __float2half2_rn(s_lJ[bb * JSTRIDE + lane]);
        const H2x4* ko = (const H2x4*)(s_oK + bb * KSTRIDE);
        const H2x4* kl = (const H2x4*)(s_lK + bb * KSTRIDE);

        __half2 a0 = z2, a1 = z2, a2 = z2, a3 = z2;

        #pragma unroll
        for (int g = 0; g < 4; g++) {       // 8 k per group
            H2x4 o4 = ko[g];                // LDS.128 broadcast
            H2x4 l4 = kl[g];

            // v = m - (oj-ok)(lj-lk) = m + (ok-oj)*(lj-lk)
            __half2 va = __hfma2(__hsub2(o4.h[0], oj2), __hsub2(lj2, l4.h[0]), m2);
            __half2 vb = __hfma2(__hsub2(o4.h[1], oj2), __hsub2(lj2, l4.h[1]), m2);
            __half2 vc = __hfma2(__hsub2(o4.h[2], oj2), __hsub2(lj2, l4.h[2]), m2);
            __half2 vd = __hfma2(__hsub2(o4.h[3], oj2), __hsub2(lj2, l4.h[3]), m2);

            a0 = __hadd2(a0, __hmax2(va, z2));
            a1 = __hadd2(a1, __hmax2(vb, z2));
            a2 = __hadd2(a2, __hmax2(vc, z2));
            a3 = __hadd2(a3, __hmax2(vd, z2));
        }

        float2 f0 = __half22float2(a0);
        float2 f1 = __half22float2(a1);
        float2 f2 = __half22float2(a2);
        float2 f3 = __half22float2(a3);
        acc += ((f0.x + f0.y) + (f1.x + f1.y)) + ((f2.x + f2.y) + (f3.x + f3.y));
    }
    acc *= w;

    // Warp reduce.
    #pragma unroll
    for (int off = 16; off > 0; off >>= 1)
        acc += __shfl_xor_sync(0xFFFFFFFFu, acc, off);
    if (lane == 0) warp_sums[wid] = acc;
    __syncthreads();

    if (t == 0) {
        float s = 0.f;
        #pragma unroll
        for (int wdx = 0; wdx < THREADS / 32; wdx++) s += warp_sums[wdx];
        atomicAdd(result, s * (1.0f / (2.0f * PN)));
    }
}

extern "C" void kernel_launch(void* const* d_in, const int* in_sizes, int n_in,
                              void* d_out, int out_size)
{
    const float* g_out    = (const float*)d_in[0];
    const float* g_label  = (const float*)d_in[1];
    const float* g_margin = (const float*)d_in[2];
    float*       result   = (float*)d_out;

    cudaMemsetAsync(result, 0, sizeof(float));
    hinge_tile_kernel<<<NBLK, THREADS>>>(g_out, g_label, g_margin, result);
}